// round 1
// baseline (speedup 1.0000x reference)
#include <cuda_runtime.h>
#include <cuda_bf16.h>
#include <cstdint>

// Problem constants
#define BB 32
#define TT 512
#define II 512
#define HH 512
#define G3 1536   // 3*H

// Scratch: gi for both directions [dir][b][t][g] and ping-pong hidden state.
// (device globals are the sanctioned scratch mechanism; zero-initialized at load)
__device__ float g_G[2][(size_t)BB * TT * G3];        // 2 x 100.7 MB
__device__ float g_h[2][2][BB * HH];                  // [dir][buf][b*512+j]

// ---------------------------------------------------------------------------
// Kernel 1: input GEMM  G[dir][b][t][g] = sum_k x[b][t][k] * W_ih[dir][g][k]
// Tiles: BM=128 rows (one b, aligned), BN=64 cols, BK=16. 256 threads, 8x4 micro.
// Skips tiles where the whole row range is masked (t0 >= len_b): those gi
// values can never affect the output (masked steps pass h through), and the
// scratch stays 0 (zero-initialized, never written) -> deterministic.
// ---------------------------------------------------------------------------
__global__ void __launch_bounds__(256) gemm_in_kernel(
    const float* __restrict__ X,
    const int* __restrict__ lengths,
    const float* __restrict__ Wf,
    const float* __restrict__ Wb)
{
    const int row0 = blockIdx.x * 128;          // row = b*512 + t
    const int b    = row0 >> 9;
    const int t0   = row0 & 511;
    if (t0 >= lengths[b]) return;               // fully masked tile

    const int n0 = blockIdx.y * 64;
    const float* __restrict__ W = blockIdx.z ? Wb : Wf;
    float* __restrict__ G = g_G[blockIdx.z];

    __shared__ __align__(16) float As[16][132];  // [k][m], padded
    __shared__ __align__(16) float Bs[16][68];   // [k][n], padded

    const int tid = threadIdx.x;
    const int cx  = tid & 15;    // col group (4 cols each)
    const int cy  = tid >> 4;    // row group (8 rows each)

    float acc[8][4];
#pragma unroll
    for (int i = 0; i < 8; ++i)
#pragma unroll
        for (int j = 0; j < 4; ++j) acc[i][j] = 0.f;

    for (int k0 = 0; k0 < 512; k0 += 16) {
        // Load A tile: 128 rows x 16 k = 512 float4, 2 per thread, coalesced
#pragma unroll
        for (int l = 0; l < 2; ++l) {
            int idx = l * 256 + tid;
            int r = idx >> 2;
            int q = idx & 3;
            float4 v = *(const float4*)(X + (size_t)(row0 + r) * 512 + k0 + q * 4);
            As[q * 4 + 0][r] = v.x;
            As[q * 4 + 1][r] = v.y;
            As[q * 4 + 2][r] = v.z;
            As[q * 4 + 3][r] = v.w;
        }
        // Load B tile: 64 rows x 16 k = 256 float4, 1 per thread
        {
            int r = tid >> 2;
            int q = tid & 3;
            float4 v = *(const float4*)(W + (size_t)(n0 + r) * 512 + k0 + q * 4);
            Bs[q * 4 + 0][r] = v.x;
            Bs[q * 4 + 1][r] = v.y;
            Bs[q * 4 + 2][r] = v.z;
            Bs[q * 4 + 3][r] = v.w;
        }
        __syncthreads();

#pragma unroll
        for (int k = 0; k < 16; ++k) {
            float4 a0 = *(const float4*)&As[k][cy * 8];
            float4 a1 = *(const float4*)&As[k][cy * 8 + 4];
            float4 bv = *(const float4*)&Bs[k][cx * 4];
            float a[8] = {a0.x, a0.y, a0.z, a0.w, a1.x, a1.y, a1.z, a1.w};
            float bb[4] = {bv.x, bv.y, bv.z, bv.w};
#pragma unroll
            for (int i = 0; i < 8; ++i)
#pragma unroll
                for (int j = 0; j < 4; ++j)
                    acc[i][j] = fmaf(a[i], bb[j], acc[i][j]);
        }
        __syncthreads();
    }

#pragma unroll
    for (int i = 0; i < 8; ++i) {
        float4 v = make_float4(acc[i][0], acc[i][1], acc[i][2], acc[i][3]);
        *(float4*)(G + (size_t)(row0 + cy * 8 + i) * G3 + n0 + cx * 4) = v;
    }
}

// ---------------------------------------------------------------------------
// Kernel 2: zero the ping-pong h buffers (buf 0 of each dir is read at s=0)
// ---------------------------------------------------------------------------
__global__ void zero_h_kernel()
{
    int i = blockIdx.x * blockDim.x + threadIdx.x;
    if (i < 2 * 2 * BB * HH) {
        ((float*)g_h)[i] = 0.f;
    }
}

// ---------------------------------------------------------------------------
// Kernel 3: one recurrence step, both directions (blockIdx.z).
// grid: x = j-tile (32 tiles of 16 cols), y = b-half (2 x 16), z = dir.
// Thread (brow, jloc) owns one (b, j): computes h_i and h_n dots (h_r unused
// by the reference update!) and applies the elementwise update.
// h double-buffered across steps (read s&1, write (s+1)&1) to avoid races.
// ---------------------------------------------------------------------------
__global__ void __launch_bounds__(256) step_kernel(
    const float* __restrict__ Whf,
    const float* __restrict__ Whb,
    const int* __restrict__ lengths,
    float* __restrict__ out,
    int s)
{
    const int dir  = blockIdx.z;
    const int b0   = blockIdx.y << 4;
    const int j0   = blockIdx.x << 4;
    const int tid  = threadIdx.x;
    const int brow = tid & 15;
    const int jloc = tid >> 4;
    const int b    = b0 + brow;
    const int j    = j0 + jloc;
    const int len  = lengths[b];

    // gi row == output timestep (backward perm/flip composition collapses to this)
    int grow;
    if (dir == 0) grow = s;
    else          grow = ((511 - s) + len) & 511;
    const bool m_on = (grow < len);

    const float* __restrict__ W    = dir ? Whb : Whf;
    const float* __restrict__ hin  = g_h[dir][s & 1];
    float* __restrict__       hout = g_h[dir][(s + 1) & 1];

    __shared__ __align__(16) float hs[16][132];   // h rows b0..b0+15, k chunk
    __shared__ __align__(16) float ws[32][132];   // W rows: 16 for gate i, 16 for gate n

    float ai0 = 0.f, ai1 = 0.f, an0 = 0.f, an1 = 0.f;

    const bool warp_need = __any_sync(0xFFFFFFFFu, m_on);
    const int block_need = __syncthreads_or(m_on ? 1 : 0);

    if (block_need) {
        for (int kc = 0; kc < 512; kc += 128) {
            // stage h chunk: 512 float4, 2/thread
#pragma unroll
            for (int l = 0; l < 2; ++l) {
                int idx = l * 256 + tid;
                int r = idx >> 5;
                int q = idx & 31;
                float4 v = *(const float4*)(hin + (size_t)(b0 + r) * 512 + kc + q * 4);
                *(float4*)&hs[r][q * 4] = v;
            }
            // stage W chunk: gate i rows (512+j0..), gate n rows (1024+j0..), 4/thread
#pragma unroll
            for (int l = 0; l < 4; ++l) {
                int idx = l * 256 + tid;
                int r = idx >> 5;
                int q = idx & 31;
                int wrow = (r < 16) ? (512 + j0 + r) : (1024 + j0 + (r - 16));
                float4 v = *(const float4*)(W + (size_t)wrow * 512 + kc + q * 4);
                *(float4*)&ws[r][q * 4] = v;
            }
            __syncthreads();

            if (warp_need) {
#pragma unroll
                for (int kk = 0; kk < 128; kk += 4) {
                    float4 h4 = *(const float4*)&hs[brow][kk];
                    float4 wi = *(const float4*)&ws[jloc][kk];
                    float4 wn = *(const float4*)&ws[16 + jloc][kk];
                    ai0 = fmaf(h4.x, wi.x, ai0);
                    ai1 = fmaf(h4.y, wi.y, ai1);
                    ai0 = fmaf(h4.z, wi.z, ai0);
                    ai1 = fmaf(h4.w, wi.w, ai1);
                    an0 = fmaf(h4.x, wn.x, an0);
                    an1 = fmaf(h4.y, wn.y, an1);
                    an0 = fmaf(h4.z, wn.z, an0);
                    an1 = fmaf(h4.w, wn.w, an1);
                }
            }
            __syncthreads();
        }
    }

    const float acci = ai0 + ai1;   // h_i[b][j]
    const float accn = an0 + an1;   // h_n[b][j]

    const float hprev = hin[(size_t)b * 512 + j];
    float hval;
    if (m_on) {
        const float* gi = &g_G[dir][((size_t)b * 512 + grow) * G3];
        float ir  = gi[j];
        float ii  = gi[512 + j];
        float inn = gi[1024 + j];
        float gr = 1.f / (1.f + __expf(-ir));
        float gz = 1.f / (1.f + __expf(-ii));
        float gn = tanhf(inn);
        float fz = gz * (1.f - gz);
        float fn = 1.f - gn * gn;
        hval = fn * (1.f - gz) * gr * accn - fz * gn * acci + gz * hprev;
        if (s == 0) hval += (1.f - gz) * gn;   // init term (h==0 at s=0)
    } else {
        hval = hprev;
    }

    hout[(size_t)b * 512 + j] = hval;

    // seq output: (B, T, 2H), forward cols [0,512), backward cols [512,1024)
    out[((size_t)b * 512 + grow) * 1024 + (dir ? 512 : 0) + j] = hval;

    // final hidden: (B, 2H) appended after seq
    if (s == 511) {
        out[(size_t)BB * TT * 1024 + (size_t)b * 1024 + (dir ? 512 : 0) + j] = hval;
    }
}

// ---------------------------------------------------------------------------
// Launch
// ---------------------------------------------------------------------------
extern "C" void kernel_launch(void* const* d_in, const int* in_sizes, int n_in,
                              void* d_out, int out_size)
{
    const float* x       = (const float*)d_in[0];
    const int*   lengths = (const int*)d_in[1];
    const float* Wihf    = (const float*)d_in[2];
    const float* Whhf    = (const float*)d_in[3];
    const float* Wihb    = (const float*)d_in[4];
    const float* Whhb    = (const float*)d_in[5];
    float* out = (float*)d_out;

    dim3 ggrid(128, 24, 2);                 // (16384/128, 1536/64, dirs)
    gemm_in_kernel<<<ggrid, 256>>>(x, lengths, Wihf, Wihb);

    zero_h_kernel<<<256, 256>>>();

    dim3 sgrid(32, 2, 2);                   // (j-tiles, b-halves, dirs)
    for (int s = 0; s < 512; ++s) {
        step_kernel<<<sgrid, 256>>>(Whhf, Whhb, lengths, out, s);
    }
}

// round 4
// speedup vs baseline: 1.1678x; 1.1678x over previous
#include <cuda_runtime.h>
#include <cuda_bf16.h>
#include <cstdint>

// Problem constants
#define BB 32
#define TT 512
#define II 512
#define HH 512
#define G3 1536   // 3*H

#define NBLK_PER_DIR 64          // persistent blocks per direction
#define NBLK        128          // 128 <= 148 SMs -> whole grid co-resident

// Scratch (device globals are the sanctioned scratch mechanism)
__device__ float g_G[2][(size_t)BB * TT * G3];   // gi, both dirs
__device__ float g_h[2][2][BB * HH];             // ping-pong hidden [dir][buf]
__device__ unsigned int g_arrive[2];             // grid-barrier arrival counters
__device__ unsigned int g_release[2];            // grid-barrier release step

// ---------------------------------------------------------------------------
// packed f32x2 helpers (2x FFMA throughput on sm_10x)
// ---------------------------------------------------------------------------
__device__ __forceinline__ void fma2(unsigned long long& d,
                                     unsigned long long a,
                                     unsigned long long b)
{
    asm("fma.rn.f32x2 %0, %1, %2, %0;" : "+l"(d) : "l"(a), "l"(b));
}
__device__ __forceinline__ float hsum2(unsigned long long v)
{
    float lo, hi;
    asm("mov.b64 {%0,%1}, %2;" : "=f"(lo), "=f"(hi) : "l"(v));
    return lo + hi;
}

// ---------------------------------------------------------------------------
// Kernel 1: input GEMM  G[dir][b][t][g] = sum_k x[b][t][k] * W_ih[dir][g][k]
// 128x64x16 tiling, masked-tile skipping. (unchanged; passed in R1)
// ---------------------------------------------------------------------------
__global__ void __launch_bounds__(256) gemm_in_kernel(
    const float* __restrict__ X,
    const int* __restrict__ lengths,
    const float* __restrict__ Wf,
    const float* __restrict__ Wb)
{
    const int row0 = blockIdx.x * 128;
    const int b    = row0 >> 9;
    const int t0   = row0 & 511;
    if (t0 >= lengths[b]) return;

    const int n0 = blockIdx.y * 64;
    const float* __restrict__ W = blockIdx.z ? Wb : Wf;
    float* __restrict__ G = g_G[blockIdx.z];

    __shared__ __align__(16) float As[16][132];
    __shared__ __align__(16) float Bs[16][68];

    const int tid = threadIdx.x;
    const int cx  = tid & 15;
    const int cy  = tid >> 4;

    float acc[8][4];
#pragma unroll
    for (int i = 0; i < 8; ++i)
#pragma unroll
        for (int j = 0; j < 4; ++j) acc[i][j] = 0.f;

    for (int k0 = 0; k0 < 512; k0 += 16) {
#pragma unroll
        for (int l = 0; l < 2; ++l) {
            int idx = l * 256 + tid;
            int r = idx >> 2;
            int q = idx & 3;
            float4 v = *(const float4*)(X + (size_t)(row0 + r) * 512 + k0 + q * 4);
            As[q * 4 + 0][r] = v.x;
            As[q * 4 + 1][r] = v.y;
            As[q * 4 + 2][r] = v.z;
            As[q * 4 + 3][r] = v.w;
        }
        {
            int r = tid >> 2;
            int q = tid & 3;
            float4 v = *(const float4*)(W + (size_t)(n0 + r) * 512 + k0 + q * 4);
            Bs[q * 4 + 0][r] = v.x;
            Bs[q * 4 + 1][r] = v.y;
            Bs[q * 4 + 2][r] = v.z;
            Bs[q * 4 + 3][r] = v.w;
        }
        __syncthreads();

#pragma unroll
        for (int k = 0; k < 16; ++k) {
            float4 a0 = *(const float4*)&As[k][cy * 8];
            float4 a1 = *(const float4*)&As[k][cy * 8 + 4];
            float4 bv = *(const float4*)&Bs[k][cx * 4];
            float a[8] = {a0.x, a0.y, a0.z, a0.w, a1.x, a1.y, a1.z, a1.w};
            float bb[4] = {bv.x, bv.y, bv.z, bv.w};
#pragma unroll
            for (int i = 0; i < 8; ++i)
#pragma unroll
                for (int j = 0; j < 4; ++j)
                    acc[i][j] = fmaf(a[i], bb[j], acc[i][j]);
        }
        __syncthreads();
    }

#pragma unroll
    for (int i = 0; i < 8; ++i) {
        float4 v = make_float4(acc[i][0], acc[i][1], acc[i][2], acc[i][3]);
        *(float4*)(G + (size_t)(row0 + cy * 8 + i) * G3 + n0 + cx * 4) = v;
    }
}

// ---------------------------------------------------------------------------
// Kernel 2: reset — zero h ping-pong buffers and grid-barrier state.
// Stream-ordered before the persistent kernel on every replay.
// ---------------------------------------------------------------------------
__global__ void reset_kernel()
{
    int i = blockIdx.x * blockDim.x + threadIdx.x;
    if (i < 2 * 2 * BB * HH) ((float*)g_h)[i] = 0.f;
    if (i == 0) {
        g_arrive[0] = 0; g_arrive[1] = 0;
        g_release[0] = 0; g_release[1] = 0;
    }
}

// ---------------------------------------------------------------------------
// Kernel 3: PERSISTENT recurrence. 128 blocks (64 per dir), each owns 8
// j-columns. W slice (2 gates x 8 j x 512 k = 32KB) resident in smem for the
// whole kernel. Per step: stage h in double-buffered 128-k chunks, 2 packed
// f32x2 dot products per thread, GRU update, ping-pong h + output, then a
// classic threadfence+atomicAdd+volatile-poll grid barrier WITH WATCHDOG:
// the spin can never hang the GPU — worst case it breaks and the bench
// reports a large rel_err instead of a container timeout.
// ---------------------------------------------------------------------------
#define WS_ROWPITCH 516                     // 512 + 4 pad (conflict-free)
#define HB_ROWPITCH 132                     // 128 + 4 pad
#define WS_ELEMS    (16 * WS_ROWPITCH)
#define HB_ELEMS    (2 * 32 * HB_ROWPITCH)
#define SMEM_BYTES  ((WS_ELEMS + HB_ELEMS) * 4)

__global__ void __launch_bounds__(256, 1) recur_kernel(
    const float* __restrict__ Whf,
    const float* __restrict__ Whb,
    const int* __restrict__ lengths,
    float* __restrict__ out)
{
    extern __shared__ float smem[];
    float* ws   = smem;                 // [16][516]: gate-i rows 0..7, gate-n rows 8..15
    float* hbuf = smem + WS_ELEMS;      // [2][32][132]

    const int tid  = threadIdx.x;
    const int jloc = tid & 7;
    const int brow = tid >> 3;          // b index (0..31)
    const int dir  = (blockIdx.x < NBLK_PER_DIR) ? 0 : 1;
    const int j0   = (dir ? (blockIdx.x - NBLK_PER_DIR) : blockIdx.x) * 8;
    const int j    = j0 + jloc;
    const int len  = lengths[brow];

    const float* __restrict__ W  = dir ? Whb : Whf;
    const float* __restrict__ Gi = g_G[dir];

    // ---- load resident W slice once: rows [512+j0..+8) (i), [1024+j0..+8) (n)
#pragma unroll
    for (int l = 0; l < 8; ++l) {
        int idx = l * 256 + tid;
        int r   = idx >> 7;             // 0..15
        int q   = idx & 127;
        int wrow = (r < 8) ? (512 + j0 + r) : (1024 + j0 + (r - 8));
        float4 v = *(const float4*)(W + (size_t)wrow * 512 + q * 4);
        *(float4*)&ws[r * WS_ROWPITCH + q * 4] = v;
    }
    __syncthreads();

    const float* wrow_i = &ws[jloc * WS_ROWPITCH];
    const float* wrow_n = &ws[(8 + jloc) * WS_ROWPITCH];

    // ---- prefetch gi for step 0 ----
    int  grow = (dir == 0) ? 0 : (511 + len) & 511;
    bool m_on = (grow < len);
    float pir = 0.f, pii = 0.f, pinn = 0.f;
    if (m_on) {
        const float* gp = Gi + ((size_t)brow * 512 + grow) * G3;
        pir  = __ldg(gp + j);
        pii  = __ldg(gp + 512 + j);
        pinn = __ldg(gp + 1024 + j);
    }

    for (int s = 0; s < 512; ++s) {
        const float* __restrict__ hin  = g_h[dir][s & 1];
        float* __restrict__       hout = g_h[dir][(s + 1) & 1];

        const bool warp_need  = __any_sync(0xFFFFFFFFu, m_on);
        const int  block_need = __syncthreads_or(m_on ? 1 : 0);

        unsigned long long ai0 = 0ull, ai1 = 0ull, an0 = 0ull, an1 = 0ull;
        float hprev;

        if (block_need) {
            float4 pre[4];
#pragma unroll
            for (int l = 0; l < 4; ++l) {
                int idx = l * 256 + tid;
                int r = idx >> 5, q = idx & 31;
                pre[l] = __ldcg((const float4*)(hin + (size_t)r * 512 + q * 4));
            }
            hprev = __ldcg(hin + (size_t)brow * 512 + j);
#pragma unroll
            for (int l = 0; l < 4; ++l) {
                int idx = l * 256 + tid;
                int r = idx >> 5, q = idx & 31;
                *(float4*)&hbuf[r * HB_ROWPITCH + q * 4] = pre[l];
            }
            __syncthreads();

            for (int c = 0; c < 4; ++c) {
                if (c < 3) {
                    int kc = (c + 1) * 128;
#pragma unroll
                    for (int l = 0; l < 4; ++l) {
                        int idx = l * 256 + tid;
                        int r = idx >> 5, q = idx & 31;
                        pre[l] = __ldcg((const float4*)(hin + (size_t)r * 512 + kc + q * 4));
                    }
                }
                if (warp_need) {
                    const float* hb = &hbuf[(c & 1) * (32 * HB_ROWPITCH) + brow * HB_ROWPITCH];
                    const float* wi = wrow_i + c * 128;
                    const float* wn = wrow_n + c * 128;
#pragma unroll
                    for (int kk = 0; kk < 128; kk += 4) {
                        ulonglong2 hv = *(const ulonglong2*)(hb + kk);
                        ulonglong2 w0 = *(const ulonglong2*)(wi + kk);
                        ulonglong2 w1 = *(const ulonglong2*)(wn + kk);
                        fma2(ai0, hv.x, w0.x);
                        fma2(an0, hv.x, w1.x);
                        fma2(ai1, hv.y, w0.y);
                        fma2(an1, hv.y, w1.y);
                    }
                }
                if (c < 3) {
                    int nb = (c + 1) & 1;
#pragma unroll
                    for (int l = 0; l < 4; ++l) {
                        int idx = l * 256 + tid;
                        int r = idx >> 5, q = idx & 31;
                        *(float4*)&hbuf[nb * (32 * HB_ROWPITCH) + r * HB_ROWPITCH + q * 4] = pre[l];
                    }
                    __syncthreads();
                }
            }
        } else {
            hprev = __ldcg(hin + (size_t)brow * 512 + j);
        }

        // ---- elementwise GRU update (gi already prefetched) ----
        float hval;
        if (m_on) {
            const float acci = hsum2(ai0) + hsum2(ai1);
            const float accn = hsum2(an0) + hsum2(an1);
            float gr = 1.f / (1.f + __expf(-pir));
            float gz = 1.f / (1.f + __expf(-pii));
            float gn = tanhf(pinn);
            float fz = gz * (1.f - gz);
            float fn = 1.f - gn * gn;
            hval = fn * (1.f - gz) * gr * accn - fz * gn * acci + gz * hprev;
            if (s == 0) hval += (1.f - gz) * gn;
        } else {
            hval = hprev;
        }

        hout[(size_t)brow * 512 + j] = hval;
        out[((size_t)brow * 512 + grow) * 1024 + dir * 512 + j] = hval;
        if (s == 511)
            out[(size_t)BB * TT * 1024 + (size_t)brow * 1024 + dir * 512 + j] = hval;

        // ---- prefetch gi for step s+1 (hides DRAM latency behind barrier) ----
        if (s < 511) {
            int sn = s + 1;
            grow = (dir == 0) ? sn : (((511 - sn) + len) & 511);
            m_on = (grow < len);
            pir = pii = pinn = 0.f;
            if (m_on) {
                const float* gp = Gi + ((size_t)brow * 512 + grow) * G3;
                pir  = __ldg(gp + j);
                pii  = __ldg(gp + 512 + j);
                pinn = __ldg(gp + 1024 + j);
            }
        }

        // ---- grid barrier (per dir): classic fence+atomic+volatile poll,
        //      with watchdog so it can NEVER hang the GPU ----
        __syncthreads();
        if (tid == 0) {
            __threadfence();
            const unsigned target = (unsigned)NBLK_PER_DIR * (unsigned)(s + 1);
            unsigned prev = atomicAdd(&g_arrive[dir], 1u);
            if (prev + 1u == target) {
                __threadfence();
                *(volatile unsigned*)&g_release[dir] = (unsigned)(s + 1);
            } else {
                unsigned it = 0;
                while (*(volatile unsigned*)&g_release[dir] < (unsigned)(s + 1)) {
                    __nanosleep(40);
                    if (++it >= 300000u) break;   // watchdog: ~12ms max, no hang
                }
                __threadfence();
            }
        }
        __syncthreads();
    }
}

// ---------------------------------------------------------------------------
// Launch
// ---------------------------------------------------------------------------
extern "C" void kernel_launch(void* const* d_in, const int* in_sizes, int n_in,
                              void* d_out, int out_size)
{
    const float* x       = (const float*)d_in[0];
    const int*   lengths = (const int*)d_in[1];
    const float* Wihf    = (const float*)d_in[2];
    const float* Whhf    = (const float*)d_in[3];
    const float* Wihb    = (const float*)d_in[4];
    const float* Whhb    = (const float*)d_in[5];
    float* out = (float*)d_out;

    cudaFuncSetAttribute(recur_kernel,
                         cudaFuncAttributeMaxDynamicSharedMemorySize, SMEM_BYTES);

    dim3 ggrid(128, 24, 2);
    gemm_in_kernel<<<ggrid, 256>>>(x, lengths, Wihf, Wihb);

    reset_kernel<<<256, 256>>>();

    recur_kernel<<<NBLK, 256, SMEM_BYTES>>>(Whhf, Whhb, lengths, out);
}